// round 16
// baseline (speedup 1.0000x reference)
#include <cuda_runtime.h>
#include <cuda_fp16.h>
#include <cstddef>
#include <cstdint>

#define NN 8192
#define DD 512
#define SCALE 0.04419417382415922f   // 1/sqrt(512)
#define SC_CAP 1024

// ---------------- scratch (static __device__ — no allocs allowed) ----------
__device__ float g_q[NN * DD];
__device__ float g_k[NN * DD];
__device__ float g_v[NN * DD];
__device__ __half g_vh[NN * DD];                      // fp16 copy of v for PV
__device__ float g_sc_spill[(size_t)NN * NN];         // worst-case scores
__device__ unsigned int g_adj[(size_t)NN * NN / 32];  // 8 MB adjacency bitmask
__device__ int g_is64;
__device__ __half g_xh[NN * DD];
__device__ __half g_xl[NN * DD];
__device__ __half g_wth[3 * DD * DD];
__device__ __half g_wtl[3 * DD * DD];
// sddmm -> pv handoff
__device__ int   g_deg[NN];
__device__ float g_invs[NN];
__device__ int   g_nbrg[(size_t)NN * SC_CAP];         // 32 MB
__device__ float g_pg[(size_t)NN * SC_CAP];           // 32 MB

// ---------------- adjacency (zero + fused dtype detect) ---------------------
__global__ void adj_zero_kernel(const unsigned int* __restrict__ w) {
    int i = blockIdx.x * blockDim.x + threadIdx.x;
    if (blockIdx.x == gridDim.x - 1) {
        __shared__ unsigned int red[256];
        unsigned int acc = 0;
        for (int j = threadIdx.x; j < 1024; j += 256) acc |= w[2 * j + 1];
        red[threadIdx.x] = acc;
        __syncthreads();
        #pragma unroll
        for (int s = 128; s > 0; s >>= 1) {
            if (threadIdx.x < s) red[threadIdx.x] |= red[threadIdx.x + s];
            __syncthreads();
        }
        if (threadIdx.x == 0) g_is64 = (red[0] == 0u) ? 1 : 0;
    }
    if (i < NN * (NN / 32)) g_adj[i] = 0u;
}

__global__ void adj_scatter_kernel(const void* __restrict__ ei, int E) {
    int e = blockIdx.x * blockDim.x + threadIdx.x;
    if (e >= E) return;
    int r, c;
    if (g_is64) {
        const long long* p = (const long long*)ei;
        r = (int)p[e];
        c = (int)p[(size_t)E + e];
    } else {
        const int* p = (const int*)ei;
        r = p[e];
        c = p[(size_t)E + e];
    }
    if ((unsigned)r >= NN || (unsigned)c >= NN) return;
    size_t bit = (size_t)r * NN + (size_t)c;
    atomicOr(&g_adj[bit >> 5], 1u << (bit & 31));
}

// ---------------- helpers ---------------------------------------------------
__device__ __forceinline__ void cp_async16(uint32_t smem_addr, const void* gptr) {
    asm volatile("cp.async.cg.shared.global [%0], [%1], 16;\n"
                 :: "r"(smem_addr), "l"(gptr));
}

__device__ __forceinline__ void ldsm_x4(uint32_t* r, uint32_t addr) {
    asm volatile("ldmatrix.sync.aligned.m8n8.x4.shared.b16 {%0,%1,%2,%3}, [%4];"
                 : "=r"(r[0]), "=r"(r[1]), "=r"(r[2]), "=r"(r[3]) : "r"(addr));
}

__device__ __forceinline__ void mma_f16(float* d, const uint32_t* a, uint32_t b0, uint32_t b1) {
    asm volatile(
        "mma.sync.aligned.m16n8k16.row.col.f32.f16.f16.f32 "
        "{%0,%1,%2,%3}, {%4,%5,%6,%7}, {%8,%9}, {%0,%1,%2,%3};\n"
        : "+f"(d[0]), "+f"(d[1]), "+f"(d[2]), "+f"(d[3])
        : "r"(a[0]), "r"(a[1]), "r"(a[2]), "r"(a[3]), "r"(b0), "r"(b1));
}

#define SWZ(row, chunk) ((((chunk) ^ (((row) >> 1) & 3)) << 4))

// ---------------- fused precompute: x hi/lo + all 3 W transposes ------------
__global__ void convAll_kernel(const float* __restrict__ x,
                               const float* __restrict__ Wq,
                               const float* __restrict__ Wk,
                               const float* __restrict__ Wv) {
    const int z = blockIdx.z;
    if (z == 0) {
        int i = blockIdx.x * 256 + threadIdx.x;
        if (i >= NN * DD / 4) return;
        float4 v = ((const float4*)x)[i];
        __half h0 = __float2half_rn(v.x), h1 = __float2half_rn(v.y);
        __half h2 = __float2half_rn(v.z), h3 = __float2half_rn(v.w);
        __half l0 = __float2half_rn(v.x - __half2float(h0));
        __half l1 = __float2half_rn(v.y - __half2float(h1));
        __half l2 = __float2half_rn(v.z - __half2float(h2));
        __half l3 = __float2half_rn(v.w - __half2float(h3));
        __half2 hp[2] = {__halves2half2(h0, h1), __halves2half2(h2, h3)};
        __half2 lp[2] = {__halves2half2(l0, l1), __halves2half2(l2, l3)};
        ((float2*)g_xh)[i] = *(float2*)hp;
        ((float2*)g_xl)[i] = *(float2*)lp;
    } else {
        if (blockIdx.x >= 256) return;
        const float* W = (z == 1) ? Wq : (z == 2) ? Wk : Wv;
        __half* hi = g_wth + (size_t)(z - 1) * DD * DD;
        __half* lo = g_wtl + (size_t)(z - 1) * DD * DD;

        __shared__ float tile[32][33];
        const int k0 = (blockIdx.x & 15) * 32, n0 = (blockIdx.x >> 4) * 32;
        const int tx = threadIdx.x & 31, ty = threadIdx.x >> 5;
        #pragma unroll
        for (int r = 0; r < 32; r += 8)
            tile[ty + r][tx] = W[(size_t)(k0 + ty + r) * DD + n0 + tx];
        __syncthreads();
        #pragma unroll
        for (int r = 0; r < 32; r += 8) {
            float v = tile[tx][ty + r];
            __half h = __float2half_rn(v);
            hi[(size_t)(n0 + ty + r) * DD + k0 + tx] = h;
            lo[(size_t)(n0 + ty + r) * DD + k0 + tx] = __float2half_rn(v - __half2float(h));
        }
    }
}

// ---------------- QKV projection: fp16 mma.sync + ldmatrix, 3-stage ring ----
#define PSTG 32768

__global__ void __launch_bounds__(256, 2)
proj_f16_kernel(const float* __restrict__ bq, float* __restrict__ oq,
                const float* __restrict__ bk, float* __restrict__ ok,
                const float* __restrict__ bv, float* __restrict__ ov,
                int zoff)
{
    extern __shared__ char dsm[];
    const uint32_t sbase = (uint32_t)__cvta_generic_to_shared(dsm);

    const int z = blockIdx.z + zoff;
    const float* bias = (z == 0) ? bq : (z == 1) ? bk : bv;
    float* C          = (z == 0) ? oq : (z == 1) ? ok : ov;

    const int t = threadIdx.x;
    const int lane = t & 31;
    const int wid  = t >> 5;
    const int warpRow = wid >> 1;
    const int warpCol = wid & 1;
    const int g  = lane >> 2;
    const int tg = lane & 3;
    const int bm = blockIdx.y;
    const int bn = blockIdx.x;

    const int lrow = t >> 1;
    const int lc0  = (t & 1) * 2;
    const __half* pAh = g_xh + (size_t)(bm * 128 + lrow) * DD;
    const __half* pAl = g_xl + (size_t)(bm * 128 + lrow) * DD;
    const __half* pBh = g_wth + (size_t)z * DD * DD + (size_t)(bn * 128 + lrow) * DD;
    const __half* pBl = g_wtl + (size_t)z * DD * DD + (size_t)(bn * 128 + lrow) * DD;

    const int rsel = (lane & 7) + ((lane >> 3) & 1) * 8;
    const int ksel = (lane >> 4) & 1;

    float d[2][8][4];
    #pragma unroll
    for (int mt = 0; mt < 2; mt++)
        #pragma unroll
        for (int nt = 0; nt < 8; nt++)
            #pragma unroll
            for (int r = 0; r < 4; r++) d[mt][nt][r] = 0.0f;

    #define LOADSTAGE(s, buf) do {                                            \
        const int _kh = (s) * 32;                                             \
        const uint32_t _sb = sbase + (buf) * PSTG;                            \
        _Pragma("unroll")                                                     \
        for (int _cc = 0; _cc < 2; _cc++) {                                   \
            const int _c = lc0 + _cc;                                         \
            const uint32_t _dst = lrow * 64 + SWZ(lrow, _c);                  \
            cp_async16(_sb + _dst,         pAh + _kh + _c * 8);               \
            cp_async16(_sb + 8192 + _dst,  pAl + _kh + _c * 8);               \
            cp_async16(_sb + 16384 + _dst, pBh + _kh + _c * 8);               \
            cp_async16(_sb + 24576 + _dst, pBl + _kh + _c * 8);               \
        }                                                                     \
        asm volatile("cp.async.commit_group;\n");                             \
    } while (0)

    LOADSTAGE(0, 0);
    LOADSTAGE(1, 1);

    const int NST = DD / 32;
    int buf = 0;
    for (int s = 0; s < NST; s++) {
        if (s < NST - 1) asm volatile("cp.async.wait_group 1;\n" ::: "memory");
        else             asm volatile("cp.async.wait_group 0;\n" ::: "memory");
        __syncthreads();

        if (s + 2 < NST) {
            int nb = buf + 2; if (nb >= 3) nb -= 3;
            LOADSTAGE(s + 2, nb);
        }

        const uint32_t sb = sbase + buf * PSTG;

        #pragma unroll
        for (int ks = 0; ks < 2; ks++) {
            const int chunk = ks * 2 + ksel;
            uint32_t ah[2][4], al[2][4];
            #pragma unroll
            for (int mt = 0; mt < 2; mt++) {
                const int rm = warpRow * 32 + mt * 16 + rsel;
                const uint32_t ao = sb + rm * 64 + SWZ(rm, chunk);
                ldsm_x4(ah[mt], ao);
                ldsm_x4(al[mt], ao + 8192);
            }
            #pragma unroll
            for (int half = 0; half < 2; half++) {
                uint32_t bh[2][4], bl[2][4];
                #pragma unroll
                for (int p = 0; p < 2; p++) {
                    const int rn = warpCol * 64 + (half * 2 + p) * 16 + rsel;
                    const uint32_t bo = sb + 16384 + rn * 64 + SWZ(rn, chunk);
                    ldsm_x4(bh[p], bo);
                    ldsm_x4(bl[p], bo + 8192);
                }
                #pragma unroll
                for (int p = 0; p < 2; p++)
                    #pragma unroll
                    for (int sub = 0; sub < 2; sub++)
                        #pragma unroll
                        for (int mt = 0; mt < 2; mt++)
                            mma_f16(d[mt][half * 4 + p * 2 + sub], ah[mt],
                                    bh[p][sub], bh[p][sub + 2]);
                #pragma unroll
                for (int p = 0; p < 2; p++)
                    #pragma unroll
                    for (int sub = 0; sub < 2; sub++)
                        #pragma unroll
                        for (int mt = 0; mt < 2; mt++)
                            mma_f16(d[mt][half * 4 + p * 2 + sub], ah[mt],
                                    bl[p][sub], bl[p][sub + 2]);
                #pragma unroll
                for (int p = 0; p < 2; p++)
                    #pragma unroll
                    for (int sub = 0; sub < 2; sub++)
                        #pragma unroll
                        for (int mt = 0; mt < 2; mt++)
                            mma_f16(d[mt][half * 4 + p * 2 + sub], al[mt],
                                    bh[p][sub], bh[p][sub + 2]);
            }
        }
        buf++; if (buf == 3) buf = 0;
    }

    #pragma unroll
    for (int mt = 0; mt < 2; mt++) {
        const int row = bm * 128 + warpRow * 32 + mt * 16 + g;
        #pragma unroll
        for (int nt = 0; nt < 8; nt++) {
            const int col = bn * 128 + warpCol * 64 + nt * 8 + 2 * tg;
            float2 bb = *(const float2*)&bias[col];
            float2 lo = {d[mt][nt][0] + bb.x, d[mt][nt][1] + bb.y};
            float2 hi = {d[mt][nt][2] + bb.x, d[mt][nt][3] + bb.y};
            *(float2*)&C[(size_t)row * DD + col]       = lo;
            *(float2*)&C[(size_t)(row + 8) * DD + col] = hi;
            if (z == 2) {
                *(__half2*)&g_vh[(size_t)row * DD + col] =
                    __floats2half2_rn(lo.x, lo.y);
                *(__half2*)&g_vh[(size_t)(row + 8) * DD + col] =
                    __floats2half2_rn(hi.x, hi.y);
            }
        }
    }
}

// ---------------- phase 1: SDDMM + softmax (stores deg/inv/nbr/p) -----------
__global__ __launch_bounds__(256)
void sddmm_kernel()
{
    const int i = blockIdx.x;
    const int t = threadIdx.x;
    const int lane = t & 31;
    const int wid  = t >> 5;

    __shared__ __align__(16) float qs[DD];
    __shared__ int   nbr[SC_CAP];
    __shared__ float sc[SC_CAP];
    __shared__ int   wsum[8];
    __shared__ float red[256];

    for (int d = t; d < DD; d += 256) qs[d] = g_q[(size_t)i * DD + d];

    unsigned word = g_adj[i * 256 + t];
    int pc = __popc(word);
    int x = pc;
    #pragma unroll
    for (int o = 1; o < 32; o <<= 1) {
        int y = __shfl_up_sync(0xffffffffu, x, o);
        if (lane >= o) x += y;
    }
    if (lane == 31) wsum[wid] = x;
    __syncthreads();
    if (t < 8) {
        int sv = wsum[t];
        #pragma unroll
        for (int o = 1; o < 8; o <<= 1) {
            int y = __shfl_up_sync(0xffu, sv, o);
            if (t >= o) sv += y;
        }
        wsum[t] = sv;
    }
    __syncthreads();
    const int deg = wsum[7];
    const int base0 = (wid ? wsum[wid - 1] : 0) + x - pc;

    if (t == 0) g_deg[i] = deg;
    if (deg == 0) return;

    if (deg <= SC_CAP) {
        {
            int base = base0;
            unsigned w = word;
            while (w) {
                int b = __ffs(w) - 1;
                w &= w - 1;
                nbr[base++] = t * 32 + b;
            }
        }
        __syncthreads();

        for (int s = wid * 2; s < deg; s += 16) {
            const bool has2 = (s + 1 < deg);
            const float4* k0 = (const float4*)&g_k[(size_t)nbr[s] * DD];
            const float4* k1 = (const float4*)&g_k[(size_t)nbr[has2 ? s + 1 : s] * DD];
            const float4* q4 = (const float4*)qs;
            float acc0 = 0.f, acc1 = 0.f;
            #pragma unroll
            for (int d4 = lane; d4 < DD / 4; d4 += 32) {
                float4 qv  = q4[d4];
                float4 kv0 = k0[d4];
                float4 kv1 = k1[d4];
                acc0 += qv.x * kv0.x + qv.y * kv0.y + qv.z * kv0.z + qv.w * kv0.w;
                acc1 += qv.x * kv1.x + qv.y * kv1.y + qv.z * kv1.z + qv.w * kv1.w;
            }
            #pragma unroll
            for (int o = 16; o > 0; o >>= 1) {
                acc0 += __shfl_xor_sync(0xffffffffu, acc0, o);
                acc1 += __shfl_xor_sync(0xffffffffu, acc1, o);
            }
            if (lane == 0) {
                sc[s] = acc0 * SCALE;
                if (has2) sc[s + 1] = acc1 * SCALE;
            }
        }
        __syncthreads();

        float m = -3.4e38f;
        for (int s = t; s < deg; s += 256) m = fmaxf(m, sc[s]);
        red[t] = m;
        __syncthreads();
        #pragma unroll
        for (int s = 128; s > 0; s >>= 1) {
            if (t < s) red[t] = fmaxf(red[t], red[t + s]);
            __syncthreads();
        }
        m = red[0];
        __syncthreads();

        float sum = 0.f;
        for (int s = t; s < deg; s += 256) {
            float p = __expf(sc[s] - m);
            sc[s] = p;
            sum += p;
        }
        red[t] = sum;
        __syncthreads();
        #pragma unroll
        for (int s = 128; s > 0; s >>= 1) {
            if (t < s) red[t] += red[t + s];
            __syncthreads();
        }
        if (t == 0) g_invs[i] = 1.0f / red[0];
        __syncthreads();

        // handoff: coalesced stores of nbr + unnormalized p
        for (int s = t; s < deg; s += 256) {
            g_nbrg[(size_t)i * SC_CAP + s] = nbr[s];
            g_pg[(size_t)i * SC_CAP + s]   = sc[s];
        }
    } else {
        // slow path (deg > 1024): full-row scores in spill
        float* scores = &g_sc_spill[(size_t)i * NN];
        for (int c = wid; c < NN; c += 8) {
            bool edge = (g_adj[i * 256 + (c >> 5)] >> (c & 31)) & 1u;
            float acc = 0.f;
            if (edge) {
                const float* kj = &g_k[(size_t)c * DD];
                for (int d = lane; d < DD; d += 32) acc += qs[d] * kj[d];
                #pragma unroll
                for (int o = 16; o > 0; o >>= 1) acc += __shfl_xor_sync(0xffffffffu, acc, o);
            }
            if (lane == 0) scores[c] = edge ? acc * SCALE : -3.4e38f;
        }
        __syncthreads();

        float m = -3.4e38f;
        for (int c = t; c < NN; c += 256) m = fmaxf(m, scores[c]);
        red[t] = m;
        __syncthreads();
        #pragma unroll
        for (int s = 128; s > 0; s >>= 1) {
            if (t < s) red[t] = fmaxf(red[t], red[t + s]);
            __syncthreads();
        }
        m = red[0];
        __syncthreads();

        float sum = 0.f;
        for (int c = t; c < NN; c += 256) {
            float p = __expf(scores[c] - m);
            scores[c] = p;
            sum += p;
        }
        red[t] = sum;
        __syncthreads();
        #pragma unroll
        for (int s = 128; s > 0; s >>= 1) {
            if (t < s) red[t] += red[t + s];
            __syncthreads();
        }
        if (t == 0) g_invs[i] = 1.0f / red[0];
    }
}

// ---------------- phase 2: PV gather (reads deg/inv/nbr/p) ------------------
__global__ __launch_bounds__(256)
void pv_kernel(float* __restrict__ out)
{
    const int i = blockIdx.x;
    const int t = threadIdx.x;

    __shared__ int   nbr[SC_CAP];
    __shared__ float sc[SC_CAP];

    const int deg = g_deg[i];

    if (deg == 0) {
        // exact uniform-softmax fallback (probability ~1e-10)
        float s0 = 0.f, s1 = 0.f;
        for (int r = 0; r < NN; r++) {
            float2 f = *(const float2*)&g_v[(size_t)r * DD + 2 * t];
            s0 += f.x; s1 += f.y;
        }
        float2 o = {s0 * (1.0f / NN), s1 * (1.0f / NN)};
        *(float2*)&out[(size_t)i * DD + 2 * t] = o;
        return;
    }

    const float inv = g_invs[i];

    if (deg <= SC_CAP) {
        for (int s = t; s < deg; s += 256) {
            nbr[s] = g_nbrg[(size_t)i * SC_CAP + s];
            sc[s]  = g_pg[(size_t)i * SC_CAP + s];
        }
        __syncthreads();

        float o0 = 0.f, o1 = 0.f;
        int s = 0;
        for (; s + 3 < deg; s += 4) {
            __half2 v0 = *(const __half2*)&g_vh[(size_t)nbr[s]     * DD + 2 * t];
            __half2 v1 = *(const __half2*)&g_vh[(size_t)nbr[s + 1] * DD + 2 * t];
            __half2 v2 = *(const __half2*)&g_vh[(size_t)nbr[s + 2] * DD + 2 * t];
            __half2 v3 = *(const __half2*)&g_vh[(size_t)nbr[s + 3] * DD + 2 * t];
            float p0 = sc[s], p1 = sc[s + 1], p2 = sc[s + 2], p3 = sc[s + 3];
            float2 f0 = __half22float2(v0);
            float2 f1 = __half22float2(v1);
            float2 f2 = __half22float2(v2);
            float2 f3 = __half22float2(v3);
            o0 += p0 * f0.x + p1 * f1.x + p2 * f2.x + p3 * f3.x;
            o1 += p0 * f0.y + p1 * f1.y + p2 * f2.y + p3 * f3.y;
        }
        for (; s < deg; s++) {
            float p = sc[s];
            float2 f = __half22float2(*(const __half2*)&g_vh[(size_t)nbr[s] * DD + 2 * t]);
            o0 += p * f.x;
            o1 += p * f.y;
        }
        float2 o = {o0 * inv, o1 * inv};
        *(float2*)&out[(size_t)i * DD + 2 * t] = o;
    } else {
        const float* scores = &g_sc_spill[(size_t)i * NN];
        float o0 = 0.f, o1 = 0.f;
        for (int c = 0; c < NN; c++) {
            float p = scores[c];
            if (p != 0.f) {
                const float* vj = &g_v[(size_t)c * DD];
                o0 += p * vj[t];
                o1 += p * vj[t + 256];
            }
        }
        out[(size_t)i * DD + t]       = o0 * inv;
        out[(size_t)i * DD + t + 256] = o1 * inv;
    }
}

// ---------------- launch ---------------------------------------------------
extern "C" void kernel_launch(void* const* d_in, const int* in_sizes, int n_in,
                              void* d_out, int out_size)
{
    const float* x  = (const float*)d_in[0];
    const void*  ei = d_in[1];
    const float* Wq = (const float*)d_in[2];
    const float* bq = (const float*)d_in[3];
    const float* Wk = (const float*)d_in[4];
    const float* bk = (const float*)d_in[5];
    const float* Wv = (const float*)d_in[6];
    const float* bv = (const float*)d_in[7];
    float* out = (float*)d_out;
    const int E = in_sizes[1] / 2;

    float *pq, *pk, *pv;
    cudaGetSymbolAddress((void**)&pq, g_q);
    cudaGetSymbolAddress((void**)&pk, g_k);
    cudaGetSymbolAddress((void**)&pv, g_v);

    static cudaStream_t s2 = nullptr;
    static cudaEvent_t evFork = nullptr, evAdj = nullptr, evQK = nullptr, evV = nullptr;
    if (!s2) {
        cudaStreamCreateWithFlags(&s2, cudaStreamNonBlocking);
        cudaEventCreateWithFlags(&evFork, cudaEventDisableTiming);
        cudaEventCreateWithFlags(&evAdj, cudaEventDisableTiming);
        cudaEventCreateWithFlags(&evQK, cudaEventDisableTiming);
        cudaEventCreateWithFlags(&evV, cudaEventDisableTiming);
        cudaFuncSetAttribute(proj_f16_kernel,
                             cudaFuncAttributeMaxDynamicSharedMemorySize, 3 * PSTG);
    }

    // fork: adjacency on side stream
    cudaEventRecord(evFork, 0);
    cudaStreamWaitEvent(s2, evFork, 0);
    adj_zero_kernel<<<(NN * (NN / 32) + 255) / 256, 256, 0, s2>>>((const unsigned int*)ei);
    adj_scatter_kernel<<<(E + 255) / 256, 256, 0, s2>>>(ei, E);
    cudaEventRecord(evAdj, s2);

    // main: precompute -> proj q,k
    dim3 gConv(NN * DD / 4 / 256, 1, 4);
    convAll_kernel<<<gConv, 256>>>(x, Wq, Wk, Wv);

    dim3 gQK(DD / 128, NN / 128, 2);
    proj_f16_kernel<<<gQK, 256, 3 * PSTG>>>(bq, pq, bk, pk, bv, pv, 0);
    cudaEventRecord(evQK, 0);

    // side: proj v AFTER qk (overlaps sddmm below)
    cudaStreamWaitEvent(s2, evQK, 0);
    dim3 gV(DD / 128, NN / 128, 1);
    proj_f16_kernel<<<gV, 256, 3 * PSTG, s2>>>(bq, pq, bk, pk, bv, pv, 2);
    cudaEventRecord(evV, s2);

    // main: sddmm (needs q,k + adjacency) — runs concurrent with proj_v
    cudaStreamWaitEvent(0, evAdj, 0);
    sddmm_kernel<<<NN, 256>>>();

    // main: pv (needs v + sddmm results)
    cudaStreamWaitEvent(0, evV, 0);
    pv_kernel<<<NN, 256>>>(out);
}

// round 17
// speedup vs baseline: 1.0601x; 1.0601x over previous
#include <cuda_runtime.h>
#include <cuda_fp16.h>
#include <cstddef>
#include <cstdint>

#define NN 8192
#define DD 512
#define SCALE 0.04419417382415922f   // 1/sqrt(512)
#define SC_CAP 1024

// ---------------- scratch (static __device__ — no allocs allowed) ----------
__device__ float g_q[NN * DD];
__device__ float g_k[NN * DD];
__device__ float g_v[NN * DD];
__device__ __half g_vh[NN * DD];                      // fp16 copy of v for PV
__device__ float g_sc_spill[(size_t)NN * NN];         // worst-case scores
__device__ unsigned int g_adj[(size_t)NN * NN / 32];  // 8 MB adjacency bitmask
__device__ int g_is64;
__device__ __half g_xh[NN * DD];
__device__ __half g_xl[NN * DD];
__device__ __half g_wth[3 * DD * DD];
__device__ __half g_wtl[3 * DD * DD];

// ---------------- adjacency (zero + fused dtype detect) ---------------------
__global__ void adj_zero_kernel(const unsigned int* __restrict__ w) {
    int i = blockIdx.x * blockDim.x + threadIdx.x;
    if (blockIdx.x == gridDim.x - 1) {
        __shared__ unsigned int red[256];
        unsigned int acc = 0;
        for (int j = threadIdx.x; j < 1024; j += 256) acc |= w[2 * j + 1];
        red[threadIdx.x] = acc;
        __syncthreads();
        #pragma unroll
        for (int s = 128; s > 0; s >>= 1) {
            if (threadIdx.x < s) red[threadIdx.x] |= red[threadIdx.x + s];
            __syncthreads();
        }
        if (threadIdx.x == 0) g_is64 = (red[0] == 0u) ? 1 : 0;
    }
    if (i < NN * (NN / 32)) g_adj[i] = 0u;
}

__global__ void adj_scatter_kernel(const void* __restrict__ ei, int E) {
    int e = blockIdx.x * blockDim.x + threadIdx.x;
    if (e >= E) return;
    int r, c;
    if (g_is64) {
        const long long* p = (const long long*)ei;
        r = (int)p[e];
        c = (int)p[(size_t)E + e];
    } else {
        const int* p = (const int*)ei;
        r = p[e];
        c = p[(size_t)E + e];
    }
    if ((unsigned)r >= NN || (unsigned)c >= NN) return;
    size_t bit = (size_t)r * NN + (size_t)c;
    atomicOr(&g_adj[bit >> 5], 1u << (bit & 31));
}

// ---------------- helpers ---------------------------------------------------
__device__ __forceinline__ void cp_async16(uint32_t smem_addr, const void* gptr) {
    asm volatile("cp.async.cg.shared.global [%0], [%1], 16;\n"
                 :: "r"(smem_addr), "l"(gptr));
}

__device__ __forceinline__ void ldsm_x4(uint32_t* r, uint32_t addr) {
    asm volatile("ldmatrix.sync.aligned.m8n8.x4.shared.b16 {%0,%1,%2,%3}, [%4];"
                 : "=r"(r[0]), "=r"(r[1]), "=r"(r[2]), "=r"(r[3]) : "r"(addr));
}

__device__ __forceinline__ void mma_f16(float* d, const uint32_t* a, uint32_t b0, uint32_t b1) {
    asm volatile(
        "mma.sync.aligned.m16n8k16.row.col.f32.f16.f16.f32 "
        "{%0,%1,%2,%3}, {%4,%5,%6,%7}, {%8,%9}, {%0,%1,%2,%3};\n"
        : "+f"(d[0]), "+f"(d[1]), "+f"(d[2]), "+f"(d[3])
        : "r"(a[0]), "r"(a[1]), "r"(a[2]), "r"(a[3]), "r"(b0), "r"(b1));
}

// 64B-row swizzle: 16B slot = chunk ^ ((row>>1)&3)
#define SWZ64(row, chunk) ((((chunk) ^ (((row) >> 1) & 3)) << 4))

// ---------------- fused precompute: x hi/lo + all 3 W transposes ------------
__global__ void convAll_kernel(const float* __restrict__ x,
                               const float* __restrict__ Wq,
                               const float* __restrict__ Wk,
                               const float* __restrict__ Wv) {
    const int z = blockIdx.z;
    if (z == 0) {
        int i = blockIdx.x * 256 + threadIdx.x;
        if (i >= NN * DD / 4) return;
        float4 v = ((const float4*)x)[i];
        __half h0 = __float2half_rn(v.x), h1 = __float2half_rn(v.y);
        __half h2 = __float2half_rn(v.z), h3 = __float2half_rn(v.w);
        __half l0 = __float2half_rn(v.x - __half2float(h0));
        __half l1 = __float2half_rn(v.y - __half2float(h1));
        __half l2 = __float2half_rn(v.z - __half2float(h2));
        __half l3 = __float2half_rn(v.w - __half2float(h3));
        __half2 hp[2] = {__halves2half2(h0, h1), __halves2half2(h2, h3)};
        __half2 lp[2] = {__halves2half2(l0, l1), __halves2half2(l2, l3)};
        ((float2*)g_xh)[i] = *(float2*)hp;
        ((float2*)g_xl)[i] = *(float2*)lp;
    } else {
        if (blockIdx.x >= 256) return;
        const float* W = (z == 1) ? Wq : (z == 2) ? Wk : Wv;
        __half* hi = g_wth + (size_t)(z - 1) * DD * DD;
        __half* lo = g_wtl + (size_t)(z - 1) * DD * DD;

        __shared__ float tile[32][33];
        const int k0 = (blockIdx.x & 15) * 32, n0 = (blockIdx.x >> 4) * 32;
        const int tx = threadIdx.x & 31, ty = threadIdx.x >> 5;
        #pragma unroll
        for (int r = 0; r < 32; r += 8)
            tile[ty + r][tx] = W[(size_t)(k0 + ty + r) * DD + n0 + tx];
        __syncthreads();
        #pragma unroll
        for (int r = 0; r < 32; r += 8) {
            float v = tile[tx][ty + r];
            __half h = __float2half_rn(v);
            hi[(size_t)(n0 + ty + r) * DD + k0 + tx] = h;
            lo[(size_t)(n0 + ty + r) * DD + k0 + tx] = __float2half_rn(v - __half2float(h));
        }
    }
}

// ---------------- QKV projection: 128x64 tile, 3 CTA/SM, 3-stage ring -------
// Stage: Ah(8K)|Al(8K)|Bh(4K)|Bl(4K) = 24KB
#define PSTG 24576

__global__ void __launch_bounds__(256, 3)
proj_f16_kernel(const float* __restrict__ bq, float* __restrict__ oq,
                const float* __restrict__ bk, float* __restrict__ ok,
                const float* __restrict__ bv, float* __restrict__ ov)
{
    extern __shared__ char dsm[];
    const uint32_t sbase = (uint32_t)__cvta_generic_to_shared(dsm);

    const int z = blockIdx.z;
    const float* bias = (z == 0) ? bq : (z == 1) ? bk : bv;
    float* C          = (z == 0) ? oq : (z == 1) ? ok : ov;

    const int t = threadIdx.x;
    const int lane = t & 31;
    const int wid  = t >> 5;
    const int warpRow = wid >> 1;       // 0..3 -> M offset *32
    const int warpCol = wid & 1;        // 0..1 -> N offset *32
    const int g  = lane >> 2;
    const int tg = lane & 3;
    const int bm = blockIdx.y;
    const int bn = blockIdx.x;

    // loaders
    const int a_row = t >> 1;           // 0..127, 2 granules each
    const int a_c0  = (t & 1) * 2;
    const int b_row = t >> 2;           // 0..63, 1 granule each
    const int b_c   = t & 3;
    const __half* pAh = g_xh + (size_t)(bm * 128 + a_row) * DD;
    const __half* pAl = g_xl + (size_t)(bm * 128 + a_row) * DD;
    const __half* pBh = g_wth + (size_t)z * DD * DD + (size_t)(bn * 64 + b_row) * DD;
    const __half* pBl = g_wtl + (size_t)z * DD * DD + (size_t)(bn * 64 + b_row) * DD;

    const int rsel = (lane & 7) + ((lane >> 3) & 1) * 8;
    const int ksel = (lane >> 4) & 1;

    float d[2][4][4];
    #pragma unroll
    for (int mt = 0; mt < 2; mt++)
        #pragma unroll
        for (int nt = 0; nt < 4; nt++)
            #pragma unroll
            for (int r = 0; r < 4; r++) d[mt][nt][r] = 0.0f;

    #define LOADSTAGE(s, buf) do {                                            \
        const int _kh = (s) * 32;                                             \
        const uint32_t _sb = sbase + (buf) * PSTG;                            \
        _Pragma("unroll")                                                     \
        for (int _cc = 0; _cc < 2; _cc++) {                                   \
            const int _c = a_c0 + _cc;                                        \
            const uint32_t _dst = a_row * 64 + SWZ64(a_row, _c);              \
            cp_async16(_sb + _dst,        pAh + _kh + _c * 8);                \
            cp_async16(_sb + 8192 + _dst, pAl + _kh + _c * 8);                \
        }                                                                     \
        {                                                                     \
            const uint32_t _dst = b_row * 64 + SWZ64(b_row, b_c);             \
            cp_async16(_sb + 16384 + _dst, pBh + _kh + b_c * 8);              \
            cp_async16(_sb + 20480 + _dst, pBl + _kh + b_c * 8);              \
        }                                                                     \
        asm volatile("cp.async.commit_group;\n");                             \
    } while (0)

    LOADSTAGE(0, 0);
    LOADSTAGE(1, 1);

    const int NST = DD / 32;   // 16
    int buf = 0;
    for (int s = 0; s < NST; s++) {
        if (s < NST - 1) asm volatile("cp.async.wait_group 1;\n" ::: "memory");
        else             asm volatile("cp.async.wait_group 0;\n" ::: "memory");
        __syncthreads();

        if (s + 2 < NST) {
            int nb = buf + 2; if (nb >= 3) nb -= 3;
            LOADSTAGE(s + 2, nb);
        }

        const uint32_t sb = sbase + buf * PSTG;

        #pragma unroll
        for (int ks = 0; ks < 2; ks++) {
            const int chunk = ks * 2 + ksel;
            uint32_t ah[2][4], al[2][4];
            #pragma unroll
            for (int mt = 0; mt < 2; mt++) {
                const int rm = warpRow * 32 + mt * 16 + rsel;
                const uint32_t ao = sb + rm * 64 + SWZ64(rm, chunk);
                ldsm_x4(ah[mt], ao);
                ldsm_x4(al[mt], ao + 8192);
            }
            uint32_t bh[2][4], bl[2][4];
            #pragma unroll
            for (int p = 0; p < 2; p++) {
                const int rn = warpCol * 32 + p * 16 + rsel;
                const uint32_t bo = sb + 16384 + rn * 64 + SWZ64(rn, chunk);
                ldsm_x4(bh[p], bo);
                ldsm_x4(bl[p], bo + 4096);
            }
            // 3-term sweeps (8 independent MMAs each)
            #pragma unroll
            for (int p = 0; p < 2; p++)
                #pragma unroll
                for (int sub = 0; sub < 2; sub++)
                    #pragma unroll
                    for (int mt = 0; mt < 2; mt++)
                        mma_f16(d[mt][p * 2 + sub], ah[mt], bh[p][sub], bh[p][sub + 2]);
            #pragma unroll
            for (int p = 0; p < 2; p++)
                #pragma unroll
                for (int sub = 0; sub < 2; sub++)
                    #pragma unroll
                    for (int mt = 0; mt < 2; mt++)
                        mma_f16(d[mt][p * 2 + sub], ah[mt], bl[p][sub], bl[p][sub + 2]);
            #pragma unroll
            for (int p = 0; p < 2; p++)
                #pragma unroll
                for (int sub = 0; sub < 2; sub++)
                    #pragma unroll
                    for (int mt = 0; mt < 2; mt++)
                        mma_f16(d[mt][p * 2 + sub], al[mt], bh[p][sub], bh[p][sub + 2]);
        }
        buf++; if (buf == 3) buf = 0;
    }

    #pragma unroll
    for (int mt = 0; mt < 2; mt++) {
        const int row = bm * 128 + warpRow * 32 + mt * 16 + g;
        #pragma unroll
        for (int nt = 0; nt < 4; nt++) {
            const int col = bn * 64 + warpCol * 32 + nt * 8 + 2 * tg;
            float2 bb = *(const float2*)&bias[col];
            float2 lo = {d[mt][nt][0] + bb.x, d[mt][nt][1] + bb.y};
            float2 hi = {d[mt][nt][2] + bb.x, d[mt][nt][3] + bb.y};
            *(float2*)&C[(size_t)row * DD + col]       = lo;
            *(float2*)&C[(size_t)(row + 8) * DD + col] = hi;
            if (z == 2) {
                *(__half2*)&g_vh[(size_t)row * DD + col] =
                    __floats2half2_rn(lo.x, lo.y);
                *(__half2*)&g_vh[(size_t)(row + 8) * DD + col] =
                    __floats2half2_rn(hi.x, hi.y);
            }
        }
    }
}

// ---------------- sparse attention: one block (256 thr) per row (R13) ------
__global__ __launch_bounds__(256)
void spattn_kernel(float* __restrict__ out)
{
    const int i = blockIdx.x;
    const int t = threadIdx.x;
    const int lane = t & 31;
    const int wid  = t >> 5;

    __shared__ __align__(16) float qs[DD];
    __shared__ int   nbr[SC_CAP];
    __shared__ float sc[SC_CAP];
    __shared__ int   wsum[8];
    __shared__ float red[256];

    for (int d = t; d < DD; d += 256) qs[d] = g_q[(size_t)i * DD + d];

    unsigned word = g_adj[i * 256 + t];
    int pc = __popc(word);
    int x = pc;
    #pragma unroll
    for (int o = 1; o < 32; o <<= 1) {
        int y = __shfl_up_sync(0xffffffffu, x, o);
        if (lane >= o) x += y;
    }
    if (lane == 31) wsum[wid] = x;
    __syncthreads();
    if (t < 8) {
        int sv = wsum[t];
        #pragma unroll
        for (int o = 1; o < 8; o <<= 1) {
            int y = __shfl_up_sync(0xffu, sv, o);
            if (t >= o) sv += y;
        }
        wsum[t] = sv;
    }
    __syncthreads();
    const int deg = wsum[7];
    const int base0 = (wid ? wsum[wid - 1] : 0) + x - pc;

    if (deg == 0) {
        float s0 = 0.f, s1 = 0.f;
        for (int r = 0; r < NN; r++) {
            float2 f = *(const float2*)&g_v[(size_t)r * DD + 2 * t];
            s0 += f.x; s1 += f.y;
        }
        float2 o = {s0 * (1.0f / NN), s1 * (1.0f / NN)};
        *(float2*)&out[(size_t)i * DD + 2 * t] = o;
        return;
    }

    if (deg <= SC_CAP) {
        {
            int base = base0;
            unsigned w = word;
            while (w) {
                int b = __ffs(w) - 1;
                w &= w - 1;
                nbr[base++] = t * 32 + b;
            }
        }
        __syncthreads();

        for (int s = wid * 2; s < deg; s += 16) {
            const bool has2 = (s + 1 < deg);
            const float4* k0 = (const float4*)&g_k[(size_t)nbr[s] * DD];
            const float4* k1 = (const float4*)&g_k[(size_t)nbr[has2 ? s + 1 : s] * DD];
            const float4* q4 = (const float4*)qs;
            float acc0 = 0.f, acc1 = 0.f;
            #pragma unroll
            for (int d4 = lane; d4 < DD / 4; d4 += 32) {
                float4 qv  = q4[d4];
                float4 kv0 = k0[d4];
                float4 kv1 = k1[d4];
                acc0 += qv.x * kv0.x + qv.y * kv0.y + qv.z * kv0.z + qv.w * kv0.w;
                acc1 += qv.x * kv1.x + qv.y * kv1.y + qv.z * kv1.z + qv.w * kv1.w;
            }
            #pragma unroll
            for (int o = 16; o > 0; o >>= 1) {
                acc0 += __shfl_xor_sync(0xffffffffu, acc0, o);
                acc1 += __shfl_xor_sync(0xffffffffu, acc1, o);
            }
            if (lane == 0) {
                sc[s] = acc0 * SCALE;
                if (has2) sc[s + 1] = acc1 * SCALE;
            }
        }
        __syncthreads();

        float m = -3.4e38f;
        for (int s = t; s < deg; s += 256) m = fmaxf(m, sc[s]);
        red[t] = m;
        __syncthreads();
        #pragma unroll
        for (int s = 128; s > 0; s >>= 1) {
            if (t < s) red[t] = fmaxf(red[t], red[t + s]);
            __syncthreads();
        }
        m = red[0];
        __syncthreads();

        float sum = 0.f;
        for (int s = t; s < deg; s += 256) {
            float p = __expf(sc[s] - m);
            sc[s] = p;
            sum += p;
        }
        red[t] = sum;
        __syncthreads();
        #pragma unroll
        for (int s = 128; s > 0; s >>= 1) {
            if (t < s) red[t] += red[t + s];
            __syncthreads();
        }
        const float inv = 1.0f / red[0];
        __syncthreads();

        float o0 = 0.f, o1 = 0.f;
        int s = 0;
        for (; s + 3 < deg; s += 4) {
            __half2 v0 = *(const __half2*)&g_vh[(size_t)nbr[s]     * DD + 2 * t];
            __half2 v1 = *(const __half2*)&g_vh[(size_t)nbr[s + 1] * DD + 2 * t];
            __half2 v2 = *(const __half2*)&g_vh[(size_t)nbr[s + 2] * DD + 2 * t];
            __half2 v3 = *(const __half2*)&g_vh[(size_t)nbr[s + 3] * DD + 2 * t];
            float p0 = sc[s], p1 = sc[s + 1], p2 = sc[s + 2], p3 = sc[s + 3];
            float2 f0 = __half22float2(v0);
            float2 f1 = __half22float2(v1);
            float2 f2 = __half22float2(v2);
            float2 f3 = __half22float2(v3);
            o0 += p0 * f0.x + p1 * f1.x + p2 * f2.x + p3 * f3.x;
            o1 += p0 * f0.y + p1 * f1.y + p2 * f2.y + p3 * f3.y;
        }
        for (; s < deg; s++) {
            float p = sc[s];
            float2 f = __half22float2(*(const __half2*)&g_vh[(size_t)nbr[s] * DD + 2 * t]);
            o0 += p * f.x;
            o1 += p * f.y;
        }
        float2 o = {o0 * inv, o1 * inv};
        *(float2*)&out[(size_t)i * DD + 2 * t] = o;
    } else {
        float* scores = &g_sc_spill[(size_t)i * NN];
        for (int c = wid; c < NN; c += 8) {
            bool edge = (g_adj[i * 256 + (c >> 5)] >> (c & 31)) & 1u;
            float acc = 0.f;
            if (edge) {
                const float* kj = &g_k[(size_t)c * DD];
                for (int d = lane; d < DD; d += 32) acc += qs[d] * kj[d];
                #pragma unroll
                for (int o = 16; o > 0; o >>= 1) acc += __shfl_xor_sync(0xffffffffu, acc, o);
            }
            if (lane == 0) scores[c] = edge ? acc * SCALE : -3.4e38f;
        }
        __syncthreads();

        float m = -3.4e38f;
        for (int c = t; c < NN; c += 256) m = fmaxf(m, scores[c]);
        red[t] = m;
        __syncthreads();
        #pragma unroll
        for (int s = 128; s > 0; s >>= 1) {
            if (t < s) red[t] = fmaxf(red[t], red[t + s]);
            __syncthreads();
        }
        m = red[0];
        __syncthreads();

        float sum = 0.f;
        for (int c = t; c < NN; c += 256) {
            float p = __expf(scores[c] - m);
            scores[c] = p;
            sum += p;
        }
        red[t] = sum;
        __syncthreads();
        #pragma unroll
        for (int s = 128; s > 0; s >>= 1) {
            if (t < s) red[t] += red[t + s];
            __syncthreads();
        }
        const float inv = 1.0f / red[0];
        __syncthreads();

        float o0 = 0.f, o1 = 0.f;
        for (int c = 0; c < NN; c++) {
            float p = scores[c];
            if (p != 0.f) {
                const float* vj = &g_v[(size_t)c * DD];
                o0 += p * vj[t];
                o1 += p * vj[t + 256];
            }
        }
        out[(size_t)i * DD + t]       = o0 * inv;
        out[(size_t)i * DD + t + 256] = o1 * inv;
    }
}

// ---------------- launch ---------------------------------------------------
extern "C" void kernel_launch(void* const* d_in, const int* in_sizes, int n_in,
                              void* d_out, int out_size)
{
    const float* x  = (const float*)d_in[0];
    const void*  ei = d_in[1];
    const float* Wq = (const float*)d_in[2];
    const float* bq = (const float*)d_in[3];
    const float* Wk = (const float*)d_in[4];
    const float* bk = (const float*)d_in[5];
    const float* Wv = (const float*)d_in[6];
    const float* bv = (const float*)d_in[7];
    float* out = (float*)d_out;
    const int E = in_sizes[1] / 2;

    float *pq, *pk, *pv;
    cudaGetSymbolAddress((void**)&pq, g_q);
    cudaGetSymbolAddress((void**)&pk, g_k);
    cudaGetSymbolAddress((void**)&pv, g_v);

    static cudaStream_t s2 = nullptr;
    static cudaEvent_t evFork = nullptr, evJoin = nullptr;
    if (!s2) {
        cudaStreamCreateWithFlags(&s2, cudaStreamNonBlocking);
        cudaEventCreateWithFlags(&evFork, cudaEventDisableTiming);
        cudaEventCreateWithFlags(&evJoin, cudaEventDisableTiming);
        cudaFuncSetAttribute(proj_f16_kernel,
                             cudaFuncAttributeMaxDynamicSharedMemorySize, 3 * PSTG);
    }

    // fork: adjacency chain on side stream
    cudaEventRecord(evFork, 0);
    cudaStreamWaitEvent(s2, evFork, 0);
    adj_zero_kernel<<<(NN * (NN / 32) + 255) / 256, 256, 0, s2>>>((const unsigned int*)ei);
    adj_scatter_kernel<<<(E + 255) / 256, 256, 0, s2>>>(ei, E);
    cudaEventRecord(evJoin, s2);

    // main chain: fused precompute -> proj -> spattn
    dim3 gConv(NN * DD / 4 / 256, 1, 4);
    convAll_kernel<<<gConv, 256>>>(x, Wq, Wk, Wv);

    dim3 gProj(DD / 64, NN / 128, 3);
    proj_f16_kernel<<<gProj, 256, 3 * PSTG>>>(bq, pq, bk, pk, bv, pv);

    cudaStreamWaitEvent(0, evJoin, 0);
    spattn_kernel<<<NN, 256>>>(out);
}